// round 7
// baseline (speedup 1.0000x reference)
#include <cuda_runtime.h>
#include <math.h>

#define GXN 128
#define GYN 128
#define NA 9
#define NCELLS (32 * 128 * 128)           // 524288
#define TPB 128
#define NWARPS (TPB / 32)                 // 4
#define CHUNK 8                            // cells per warp-chunk
#define CHUNKS 4                           // chunks per warp
#define WARP_CELLS (CHUNK * CHUNKS)        // 32
#define BLOCK_CELLS (WARP_CELLS * NWARPS)  // 128
#define NBLOCKS (NCELLS / BLOCK_CELLS)     // 4096
#define CHUNK_FLOATS (CHUNK * 45)          // 360
#define CHUNK_F4 (CHUNK_FLOATS / 4)        // 90

__device__ double g_acc[5];
__device__ unsigned int g_count = 0;

__device__ __forceinline__ unsigned smem_u32(const void* p) {
    return (unsigned)__cvta_generic_to_shared(p);
}
#define CP_ASYNC_16(dst_u32, src_ptr) \
    asm volatile("cp.async.cg.shared.global [%0], [%1], 16;" :: "r"(dst_u32), "l"(src_ptr))
#define CP_COMMIT() asm volatile("cp.async.commit_group;")
#define CP_WAIT(n)  asm volatile("cp.async.wait_group %0;" :: "n"(n))

// Stage one 8-cell chunk (360 floats = 90 float4) with one warp.
__device__ __forceinline__ void stage_chunk(const float* __restrict__ out,
                                            int cellBase, float* buf, int lane)
{
    const float4* src = reinterpret_cast<const float4*>(out + (size_t)cellBase * 45);
    const unsigned dst = smem_u32(buf);
    #pragma unroll
    for (int r = 0; r < 2; r++) {
        const int idx = lane + r * 32;
        CP_ASYNC_16(dst + idx * 16, src + idx);
    }
    {
        const int idx = lane + 64;     // 90 = 2*32 + 26
        if (idx < CHUNK_F4) CP_ASYNC_16(dst + idx * 16, src + idx);
    }
}

// Prefetch target fields (st0..3 + st5) for one chunk into registers.
__device__ __forceinline__ void fetch_tgt(const float* __restrict__ target,
                                          int chunkBase, int lane,
                                          float2& st01, float2& st23, float& st5)
{
    if (lane < CHUNK) {
        const float* st = target + (size_t)(chunkBase + lane) * 18;
        st01 = __ldg(reinterpret_cast<const float2*>(st));
        st23 = __ldg(reinterpret_cast<const float2*>(st + 2));
        st5  = __ldg(st + 5);
    }
}

__global__ __launch_bounds__(TPB, 12) void loss_kernel(
    const float* __restrict__ out,
    const float* __restrict__ target,
    float* __restrict__ o)
{
    extern __shared__ float s_buf[];      // NWARPS * 2 * 360 floats = 11520 B

    // Compacted per-pos-cell params: ax1, ax2, ay1, ay2, atana, zx, zy, cell-idx
    __shared__ float s_cellp[NWARPS][CHUNK][8];   // 1024 B
    __shared__ float s_red[NWARPS][5];
    __shared__ int s_islast;

    const int tid = threadIdx.x;
    const int warp = tid >> 5;
    const int lane = tid & 31;
    const unsigned FULL = 0xFFFFFFFFu;

    const int warpBase = blockIdx.x * BLOCK_CELLS + warp * WARP_CELLS;
    float* wbuf = s_buf + warp * (2 * CHUNK_FLOATS);

    // ---- Prologue: stage chunks 0,1; prefetch target of chunk 0 ----
    stage_chunk(out, warpBase + 0 * CHUNK, wbuf, lane);
    CP_COMMIT();
    stage_chunk(out, warpBase + 1 * CHUNK, wbuf + CHUNK_FLOATS, lane);
    CP_COMMIT();

    float2 st01_cur = make_float2(0.f, 0.f), st23_cur = make_float2(0.f, 0.f);
    float st5_cur = 0.0f;
    fetch_tgt(target, warpBase, lane, st01_cur, st23_cur, st5_cur);

    float acc_allloss = 0.0f;
    float acc_jbb = 0.0f;
    float acc_huhuh = 0.0f;
    float acc_zsd = 0.0f;
    float acc_npos = 0.0f;

    const float FOUR_OVER_PI2 = 4.0f / (3.14159265358979323846f * 3.14159265358979323846f);

    #pragma unroll
    for (int k = 0; k < CHUNKS; k++) {
        const int chunkBase = warpBase + k * CHUNK;
        float* buf = wbuf + (k & 1) * CHUNK_FLOATS;

        // Prefetch next chunk's target fields before blocking on the copy
        float2 st01_next = make_float2(0.f, 0.f), st23_next = make_float2(0.f, 0.f);
        float st5_next = 0.0f;
        if (k + 1 < CHUNKS)
            fetch_tgt(target, chunkBase + CHUNK, lane, st01_next, st23_next, st5_next);

        if (k == CHUNKS - 1) { CP_WAIT(0); } else { CP_WAIT(1); }
        __syncwarp();

        const bool provider_pos = (lane < CHUNK) && (st5_cur > 0.8f);
        const unsigned m = __ballot_sync(FULL, provider_pos) & 0xFFu;
        const int nP = __popc(m);

        // ---- Providers: per-pos-cell invariants from registers (no mem latency) ----
        if (provider_pos) {
            const int off = __popc(m & ((1u << lane) - 1u));
            const int cellc = chunkBase + lane;
            const int gy = cellc & 127;
            const int gx = (cellc >> 7) & 127;

            const float ax1 = st01_cur.x - st23_cur.x * 0.5f;
            const float ax2 = st01_cur.x + st23_cur.x * 0.5f;
            const float ay1 = st01_cur.y - st23_cur.y * 0.5f;
            const float ay2 = st01_cur.y + st23_cur.y * 0.5f;
            const float atana = atanf(__fdividef(ax2 - ax1, ay2 - ay1));
            const float zx = (float)gx * (1.0f / GXN) + 1.0f / (2.0f * GXN);
            const float zy = (float)gy * (1.0f / GYN) + 1.0f / (2.0f * GYN);

            float* p = s_cellp[warp][off];
            p[0] = ax1; p[1] = ax2; p[2] = ay1; p[3] = ay2;
            p[4] = atana; p[5] = zx; p[6] = zy;
            p[7] = __int_as_float(lane);
            acc_npos += 1.0f;
        }

        // ---- Negative path: 4 lanes per cell, anchors split 2/2/2/3 ----
        {
            const int c = lane & 7;
            const int grp = lane >> 3;           // 0..3
            const bool cpos = (m >> c) & 1u;
            if (!cpos) {
                const float* s = buf + c * 45;
                const int a0 = grp * 2;
                float obj = s[a0 * 5 + 4];
                acc_zsd += obj * obj;
                obj = s[(a0 + 1) * 5 + 4];
                acc_zsd += obj * obj;
                if (grp == 3) {
                    obj = s[8 * 5 + 4];
                    acc_zsd += obj * obj;
                }
            }
        }
        __syncwarp();   // providers' s_cellp visible

        // ---- Heavy path: nP*9 work items, 32 per pass ----
        const int items = nP * NA;
        for (int base2 = 0; base2 < items; base2 += 32) {
            const int i = base2 + lane;
            if (i < items) {
                const int r = i / 9;
                const int a = i - r * 9;
                const float* p = s_cellp[warp][r];
                const float ax1 = p[0], ax2 = p[1], ay1 = p[2], ay2 = p[3];
                const float atana = p[4], zx = p[5], zy = p[6];
                const int c = __float_as_int(p[7]);

                const float* s = buf + c * 45 + a * 5;
                const float o0 = s[0];
                const float o1 = s[1];
                const float o2 = s[2];
                const float o3 = s[3];
                const float obj = s[4];

                const float area_a = (ax2 - ax1) * (ay2 - ay1);
                const float acx = (ax1 + ax2) * 0.5f;
                const float acy = (ay1 + ay2) * 0.5f;

                const float bcx = o0 - 0.5f + zx;
                const float bcy = o1 - 0.5f + zy;
                const float bw  = o2 - 0.5f + (1.0f / GXN);
                const float bh  = o3 - 0.5f + (1.0f / GYN);
                const float bx1 = bcx - bw * 0.5f;
                const float bx2 = bcx + bw * 0.5f;
                const float by1 = bcy - bh * 0.5f;
                const float by2 = bcy + bh * 0.5f;

                const float iw = fminf(ax2, bx2) - fmaxf(ax1, bx1);
                const float ih = fminf(ay2, by2) - fmaxf(ay1, by1);
                const float cross = (iw > 0.0f && ih > 0.0f) ? iw * ih : 0.0f;
                const float area_b = (bx2 - bx1) * (by2 - by1);
                const float uni = area_a + area_b - cross;
                const float iou = __fdividef(cross, uni + 1e-6f);

                const float dx = bcx - acx;
                const float dy = bcy - acy;
                const float d2 = dx * dx + dy * dy;

                const float cw = fmaxf(ax2, bx2) - fminf(ax1, bx1);
                const float ch = fmaxf(ay2, by2) - fminf(ay1, by1);
                const float c2 = cw * cw + ch * ch;

                const float diou = iou - __fdividef(d2, c2);

                const float da = atana - atanf(__fdividef(bx2 - bx1, by2 - by1));
                const float v = FOUR_OVER_PI2 * da * da;
                const float alpha = __fdividef(v, 1.0f - iou + v);
                const float los = 1.0f - (diou - alpha * v);

                const float om = 1.0f - obj;
                acc_allloss += los + om;
                acc_jbb += iou;
                acc_huhuh += om;
                acc_zsd += om * om;
            }
        }
        __syncwarp();   // buffer free for reuse

        if (k + 2 < CHUNKS)
            stage_chunk(out, warpBase + (k + 2) * CHUNK, buf, lane);
        CP_COMMIT();

        st01_cur = st01_next;
        st23_cur = st23_next;
        st5_cur = st5_next;
    }

    // ---- Block reduction: 4 sums + pos count ----
    float vals[5];
    vals[0] = acc_allloss;
    vals[1] = acc_jbb;
    vals[2] = acc_huhuh;
    vals[3] = acc_zsd;
    vals[4] = acc_npos;

    #pragma unroll
    for (int kk = 0; kk < 5; kk++) {
        float v = vals[kk];
        v += __shfl_xor_sync(FULL, v, 16);
        v += __shfl_xor_sync(FULL, v, 8);
        v += __shfl_xor_sync(FULL, v, 4);
        v += __shfl_xor_sync(FULL, v, 2);
        v += __shfl_xor_sync(FULL, v, 1);
        vals[kk] = v;
    }
    if (lane == 0) {
        #pragma unroll
        for (int kk = 0; kk < 5; kk++) s_red[warp][kk] = vals[kk];
    }
    __syncthreads();

    if (warp == 0 && lane < 5) {
        float v = 0.0f;
        #pragma unroll
        for (int w = 0; w < NWARPS; w++) v += s_red[w][lane];
        atomicAdd(&g_acc[lane], (double)v);
    }
    __syncthreads();

    // ---- Last block finalizes and resets for next graph replay ----
    if (tid == 0) {
        __threadfence();
        const unsigned done = atomicAdd(&g_count, 1u);
        s_islast = (done == (unsigned)(gridDim.x - 1)) ? 1 : 0;
    }
    __syncthreads();

    if (s_islast && tid == 0) {
        const double a0 = atomicAdd(&g_acc[0], 0.0);
        const double a1 = atomicAdd(&g_acc[1], 0.0);
        const double a2 = atomicAdd(&g_acc[2], 0.0);
        const double a3 = atomicAdd(&g_acc[3], 0.0);
        const double npos = atomicAdd(&g_acc[4], 0.0);

        const double jsq = npos * (double)NA;
        const double qit = ((double)NCELLS - npos) * (double)NA;
        o[0] = (float)(a0 / jsq + a3 / (jsq + qit));
        o[1] = (float)(a1 / jsq);
        o[2] = (float)(a2 / jsq);

        g_acc[0] = 0.0; g_acc[1] = 0.0; g_acc[2] = 0.0;
        g_acc[3] = 0.0; g_acc[4] = 0.0;
        __threadfence();
        g_count = 0u;
    }
}

extern "C" void kernel_launch(void* const* d_in, const int* in_sizes, int n_in,
                              void* d_out, int out_size) {
    const float* out_t = (const float*)d_in[0];
    const float* target = (const float*)d_in[1];
    float* o = (float*)d_out;

    const int smem_bytes = NWARPS * 2 * CHUNK_FLOATS * (int)sizeof(float); // 11520
    static int configured = 0;
    if (!configured) {
        cudaFuncSetAttribute(loss_kernel,
                             cudaFuncAttributeMaxDynamicSharedMemorySize,
                             smem_bytes);
        configured = 1;
    }
    loss_kernel<<<NBLOCKS, TPB, smem_bytes>>>(out_t, target, o);
}

// round 8
// speedup vs baseline: 1.0446x; 1.0446x over previous
#include <cuda_runtime.h>
#include <math.h>

#define GXN 128
#define GYN 128
#define NA 9
#define NCELLS (32 * 128 * 128)            // 524288
#define TPB 128
#define NWARPS (TPB / 32)                  // 4
#define WARP_CELLS 32
#define BLOCK_CELLS (WARP_CELLS * NWARPS)  // 128
#define NBLOCKS (NCELLS / BLOCK_CELLS)     // 4096
#define WARP_FLOATS (WARP_CELLS * 45)      // 1440
#define WARP_F4 (WARP_FLOATS / 4)          // 360

__device__ double g_acc[5];
__device__ unsigned int g_count = 0;

__device__ __forceinline__ unsigned smem_u32(const void* p) {
    return (unsigned)__cvta_generic_to_shared(p);
}
#define CP_ASYNC_16(dst_u32, src_ptr) \
    asm volatile("cp.async.cg.shared.global [%0], [%1], 16;" :: "r"(dst_u32), "l"(src_ptr))
#define CP_COMMIT() asm volatile("cp.async.commit_group;")
#define CP_WAIT(n)  asm volatile("cp.async.wait_group %0;" :: "n"(n))

__global__ __launch_bounds__(TPB, 8) void loss_kernel(
    const float* __restrict__ out,
    const float* __restrict__ target,
    float* __restrict__ o)
{
    extern __shared__ float s_buf[];   // NWARPS * 1440 floats = 23040 B

    // Compacted per-pos-cell params: ax1, ax2, ay1, ay2, atana, zx, zy, smem-word-offset
    __shared__ float s_cellp[NWARPS][WARP_CELLS][8];   // 4096 B
    __shared__ float s_red[NWARPS][5];
    __shared__ int s_islast;

    const int tid = threadIdx.x;
    const int warp = tid >> 5;
    const int lane = tid & 31;
    const unsigned FULL = 0xFFFFFFFFu;

    const int warpBase = blockIdx.x * BLOCK_CELLS + warp * WARP_CELLS;
    float* wbuf = s_buf + warp * WARP_FLOATS;

    // ---- Stage 32 cells (1440 floats = 360 float4) in one async batch ----
    {
        const float4* src = reinterpret_cast<const float4*>(out + (size_t)warpBase * 45);
        const unsigned dst = smem_u32(wbuf);
        #pragma unroll
        for (int r = 0; r < 11; r++) {
            const int idx = lane + r * 32;
            CP_ASYNC_16(dst + idx * 16, src + idx);
        }
        if (lane < WARP_F4 - 352) {                // 360 = 11*32 + 8
            const int idx = lane + 352;
            CP_ASYNC_16(dst + idx * 16, src + idx);
        }
        CP_COMMIT();
    }

    // ---- Per-lane target fields for own cell (issued before the wait) ----
    const int cellc = warpBase + lane;
    const float* st = target + (size_t)cellc * 18;
    const float2 st01 = __ldg(reinterpret_cast<const float2*>(st));
    const float2 st23 = __ldg(reinterpret_cast<const float2*>(st + 2));
    const float st5 = __ldg(st + 5);

    CP_WAIT(0);
    __syncwarp();

    const bool pos = st5 > 0.8f;
    const unsigned m = __ballot_sync(FULL, pos);
    const int nP = __popc(m);

    float acc_allloss = 0.0f;
    float acc_jbb = 0.0f;
    float acc_huhuh = 0.0f;
    float acc_zsd = 0.0f;
    float acc_npos = 0.0f;

    const float FOUR_OVER_PI2 = 4.0f / (3.14159265358979323846f * 3.14159265358979323846f);

    if (pos) {
        // ---- Provider: per-pos-cell invariants into compacted slot ----
        const int off = __popc(m & ((1u << lane) - 1u));
        const int gy = cellc & 127;
        const int gx = (cellc >> 7) & 127;

        const float ax1 = st01.x - st23.x * 0.5f;
        const float ax2 = st01.x + st23.x * 0.5f;
        const float ay1 = st01.y - st23.y * 0.5f;
        const float ay2 = st01.y + st23.y * 0.5f;
        const float atana = atanf(__fdividef(ax2 - ax1, ay2 - ay1));
        const float zx = (float)gx * (1.0f / GXN) + 1.0f / (2.0f * GXN);
        const float zy = (float)gy * (1.0f / GYN) + 1.0f / (2.0f * GYN);

        float* p = s_cellp[warp][off];
        p[0] = ax1; p[1] = ax2; p[2] = ay1; p[3] = ay2;
        p[4] = atana; p[5] = zx; p[6] = zy;
        p[7] = __int_as_float(lane * 45);
        acc_npos = 1.0f;
    } else {
        // ---- Negative path: own cell's 9 obj values ----
        const float* s = wbuf + lane * 45;
        #pragma unroll
        for (int a = 0; a < NA; a++) {
            const float obj = s[a * 5 + 4];
            acc_zsd += obj * obj;
        }
    }
    __syncwarp();   // providers' s_cellp visible

    // ---- Heavy sweep: nP*9 work items batched across all 32 cells ----
    const int items = nP * NA;
    for (int b = 0; b < items; b += 32) {
        const int i = b + lane;
        if (i < items) {
            const int r = i / 9;
            const int a = i - r * 9;
            const float* p = s_cellp[warp][r];
            const float ax1 = p[0], ax2 = p[1], ay1 = p[2], ay2 = p[3];
            const float atana = p[4], zx = p[5], zy = p[6];
            const int coff = __float_as_int(p[7]);

            const float* s = wbuf + coff + a * 5;
            const float o0 = s[0];
            const float o1 = s[1];
            const float o2 = s[2];
            const float o3 = s[3];
            const float obj = s[4];

            const float area_a = (ax2 - ax1) * (ay2 - ay1);
            const float acx = (ax1 + ax2) * 0.5f;
            const float acy = (ay1 + ay2) * 0.5f;

            const float bcx = o0 - 0.5f + zx;
            const float bcy = o1 - 0.5f + zy;
            const float bw  = o2 - 0.5f + (1.0f / GXN);
            const float bh  = o3 - 0.5f + (1.0f / GYN);
            const float bx1 = bcx - bw * 0.5f;
            const float bx2 = bcx + bw * 0.5f;
            const float by1 = bcy - bh * 0.5f;
            const float by2 = bcy + bh * 0.5f;

            const float iw = fminf(ax2, bx2) - fmaxf(ax1, bx1);
            const float ih = fminf(ay2, by2) - fmaxf(ay1, by1);
            const float cross = (iw > 0.0f && ih > 0.0f) ? iw * ih : 0.0f;
            const float area_b = (bx2 - bx1) * (by2 - by1);
            const float uni = area_a + area_b - cross;
            const float iou = __fdividef(cross, uni + 1e-6f);

            const float dx = bcx - acx;
            const float dy = bcy - acy;
            const float d2 = dx * dx + dy * dy;

            const float cw = fmaxf(ax2, bx2) - fminf(ax1, bx1);
            const float ch = fmaxf(ay2, by2) - fminf(ay1, by1);
            const float c2 = cw * cw + ch * ch;

            const float diou = iou - __fdividef(d2, c2);

            const float da = atana - atanf(__fdividef(bx2 - bx1, by2 - by1));
            const float v = FOUR_OVER_PI2 * da * da;
            const float alpha = __fdividef(v, 1.0f - iou + v);
            const float los = 1.0f - (diou - alpha * v);

            const float om = 1.0f - obj;
            acc_allloss += los + om;
            acc_jbb += iou;
            acc_huhuh += om;
            acc_zsd += om * om;
        }
    }

    // ---- Block reduction: 4 sums + pos count ----
    float vals[5];
    vals[0] = acc_allloss;
    vals[1] = acc_jbb;
    vals[2] = acc_huhuh;
    vals[3] = acc_zsd;
    vals[4] = acc_npos;

    #pragma unroll
    for (int kk = 0; kk < 5; kk++) {
        float v = vals[kk];
        v += __shfl_xor_sync(FULL, v, 16);
        v += __shfl_xor_sync(FULL, v, 8);
        v += __shfl_xor_sync(FULL, v, 4);
        v += __shfl_xor_sync(FULL, v, 2);
        v += __shfl_xor_sync(FULL, v, 1);
        vals[kk] = v;
    }
    if (lane == 0) {
        #pragma unroll
        for (int kk = 0; kk < 5; kk++) s_red[warp][kk] = vals[kk];
    }
    __syncthreads();

    if (warp == 0 && lane < 5) {
        float v = 0.0f;
        #pragma unroll
        for (int w = 0; w < NWARPS; w++) v += s_red[w][lane];
        atomicAdd(&g_acc[lane], (double)v);
    }
    __syncthreads();

    // ---- Last block finalizes and resets for next graph replay ----
    if (tid == 0) {
        __threadfence();
        const unsigned done = atomicAdd(&g_count, 1u);
        s_islast = (done == (unsigned)(gridDim.x - 1)) ? 1 : 0;
    }
    __syncthreads();

    if (s_islast && tid == 0) {
        const double a0 = atomicAdd(&g_acc[0], 0.0);
        const double a1 = atomicAdd(&g_acc[1], 0.0);
        const double a2 = atomicAdd(&g_acc[2], 0.0);
        const double a3 = atomicAdd(&g_acc[3], 0.0);
        const double npos = atomicAdd(&g_acc[4], 0.0);

        const double jsq = npos * (double)NA;
        const double qit = ((double)NCELLS - npos) * (double)NA;
        o[0] = (float)(a0 / jsq + a3 / (jsq + qit));
        o[1] = (float)(a1 / jsq);
        o[2] = (float)(a2 / jsq);

        g_acc[0] = 0.0; g_acc[1] = 0.0; g_acc[2] = 0.0;
        g_acc[3] = 0.0; g_acc[4] = 0.0;
        __threadfence();
        g_count = 0u;
    }
}

extern "C" void kernel_launch(void* const* d_in, const int* in_sizes, int n_in,
                              void* d_out, int out_size) {
    const float* out_t = (const float*)d_in[0];
    const float* target = (const float*)d_in[1];
    float* o = (float*)d_out;

    const int smem_bytes = NWARPS * WARP_FLOATS * (int)sizeof(float); // 23040
    static int configured = 0;
    if (!configured) {
        cudaFuncSetAttribute(loss_kernel,
                             cudaFuncAttributeMaxDynamicSharedMemorySize,
                             smem_bytes);
        configured = 1;
    }
    loss_kernel<<<NBLOCKS, TPB, smem_bytes>>>(out_t, target, o);
}